// round 3
// baseline (speedup 1.0000x reference)
#include <cuda_runtime.h>

#define NN 50000
#define E0 800000
#define ET 850000

// ---------------- scratch (static device globals; no allocation) ----------------
__device__ float    g_xw1[NN * 64];
__device__ float    g_als1[NN * 8];
__device__ float    g_ald1[NN * 8];
__device__ unsigned g_emax1[NN * 8];
__device__ float    g_den1[NN * 8];
__device__ float    g_h1[NN * 64];
__device__ float    g_xw2[NN * 128];
__device__ float    g_als2[NN * 8];
__device__ float    g_ald2[NN * 8];
__device__ unsigned g_emax2[NN * 8];
__device__ float    g_den2[NN * 8];
__device__ float    g_h2[NN * 128];
__device__ float    g_alpha1[(size_t)ET * 8];   // layer-1 e_exp, then alpha (output 2)
__device__ float    g_eexp2[(size_t)ET * 8];    // layer-2 e_exp

// ---------------- helpers ----------------
__device__ __forceinline__ unsigned fkey(float f) {
    unsigned u = __float_as_uint(f);
    return (u & 0x80000000u) ? ~u : (u | 0x80000000u);
}
__device__ __forceinline__ float funkey(unsigned k) {
    unsigned u = (k & 0x80000000u) ? (k & 0x7fffffffu) : ~k;
    return __uint_as_float(u);
}
__device__ __forceinline__ void red4(float* p, float a, float b, float c, float d) {
    asm volatile("red.global.add.v4.f32 [%0], {%1,%2,%3,%4};"
                 :: "l"(p), "f"(a), "f"(b), "f"(c), "f"(d) : "memory");
}
// edge_index is int32 (JAX default x64-disabled demotes int64 -> int32)
__device__ __forceinline__ bool edge_sd(const int* __restrict__ ei, int e, int& s, int& d) {
    if (e < E0) { s = ei[e]; d = ei[E0 + e]; }
    else        { s = e - E0; d = s; }
    return ((unsigned)s < NN) && ((unsigned)d < NN);
}

// ---------------- GEMM1: x[NN,256] @ W1[256,64] -> g_xw1 ----------------
__global__ __launch_bounds__(256) void k_gemm1(const float* __restrict__ A,
                                               const float* __restrict__ B,
                                               float* __restrict__ C) {
    __shared__ float As[32][68];
    __shared__ float Bs[32][68];
    int tid = threadIdx.x;
    int tx = tid & 15, ty = tid >> 4;
    int bm = blockIdx.x * 64;
    float acc[4][4] = {};
    for (int k0 = 0; k0 < 256; k0 += 32) {
#pragma unroll
        for (int i = 0; i < 8; i++) {
            int idx = tid + i * 256;                    // 2048 elems each tile
            int m = idx >> 5, k = idx & 31;
            int row = bm + m;
            As[k][m] = (row < NN) ? A[row * 256 + k0 + k] : 0.f;
            int k2 = idx >> 6, n2 = idx & 63;
            Bs[k2][n2] = B[(k0 + k2) * 64 + n2];
        }
        __syncthreads();
#pragma unroll
        for (int k = 0; k < 32; k++) {
            float4 a4 = *(const float4*)&As[k][ty * 4];
            float4 b4 = *(const float4*)&Bs[k][tx * 4];
            float av[4] = {a4.x, a4.y, a4.z, a4.w};
            float bv[4] = {b4.x, b4.y, b4.z, b4.w};
#pragma unroll
            for (int i = 0; i < 4; i++)
#pragma unroll
                for (int j = 0; j < 4; j++) acc[i][j] += av[i] * bv[j];
        }
        __syncthreads();
    }
#pragma unroll
    for (int i = 0; i < 4; i++) {
        int row = bm + ty * 4 + i;
        if (row < NN) {
            float4 st = make_float4(acc[i][0], acc[i][1], acc[i][2], acc[i][3]);
            *(float4*)&C[row * 64 + tx * 4] = st;
        }
    }
}

// ---------------- GEMM2: elu(h1+b1)[NN,64] @ W2[64,128] -> g_xw2 ----------------
__global__ __launch_bounds__(256) void k_gemm2(const float* __restrict__ A,
                                               const float* __restrict__ bias1,
                                               const float* __restrict__ B,
                                               float* __restrict__ C) {
    __shared__ float As[32][68];
    __shared__ float Bs[32][132];
    int tid = threadIdx.x;
    int tx = tid & 15, ty = tid >> 4;
    int bm = blockIdx.x * 64;
    float acc[4][8] = {};
    for (int k0 = 0; k0 < 64; k0 += 32) {
#pragma unroll
        for (int i = 0; i < 8; i++) {
            int idx = tid + i * 256;                    // 64x32 A tile
            int m = idx >> 5, k = idx & 31;
            int row = bm + m;
            float v = 0.f;
            if (row < NN) {
                v = A[row * 64 + k0 + k] + bias1[k0 + k];
                v = v > 0.f ? v : expm1f(v);           // ELU
            }
            As[k][m] = v;
        }
#pragma unroll
        for (int i = 0; i < 16; i++) {
            int idx = tid + i * 256;                    // 32x128 B tile
            int k = idx >> 7, n = idx & 127;
            Bs[k][n] = B[(k0 + k) * 128 + n];
        }
        __syncthreads();
#pragma unroll
        for (int k = 0; k < 32; k++) {
            float4 a4  = *(const float4*)&As[k][ty * 4];
            float4 b40 = *(const float4*)&Bs[k][tx * 8];
            float4 b41 = *(const float4*)&Bs[k][tx * 8 + 4];
            float av[4] = {a4.x, a4.y, a4.z, a4.w};
            float bv[8] = {b40.x, b40.y, b40.z, b40.w, b41.x, b41.y, b41.z, b41.w};
#pragma unroll
            for (int i = 0; i < 4; i++)
#pragma unroll
                for (int j = 0; j < 8; j++) acc[i][j] += av[i] * bv[j];
        }
        __syncthreads();
    }
#pragma unroll
    for (int i = 0; i < 4; i++) {
        int row = bm + ty * 4 + i;
        if (row < NN) {
            *(float4*)&C[row * 128 + tx * 8]     = make_float4(acc[i][0], acc[i][1], acc[i][2], acc[i][3]);
            *(float4*)&C[row * 128 + tx * 8 + 4] = make_float4(acc[i][4], acc[i][5], acc[i][6], acc[i][7]);
        }
    }
}

// ---------------- attention logits: als/ald[n,h] = <xw[n,h,:], a[h,:]> ----------------
template <int D>
__global__ __launch_bounds__(256) void k_attn(const float* __restrict__ xw,
                                              const float* __restrict__ as_,
                                              const float* __restrict__ ad_,
                                              float* __restrict__ als,
                                              float* __restrict__ ald) {
    int t = blockIdx.x * 256 + threadIdx.x;
    if (t >= NN * 8) return;
    int n = t >> 3, h = t & 7;
    const float* row = xw + (size_t)n * 8 * D + h * D;
    float s = 0.f, d = 0.f;
#pragma unroll
    for (int i = 0; i < D; i++) {
        float v = __ldg(row + i);
        s += v * __ldg(as_ + h * D + i);
        d += v * __ldg(ad_ + h * D + i);
    }
    als[t] = s;
    ald[t] = d;
}

// ---------------- edge pass A: segment max ----------------
__global__ __launch_bounds__(256) void k_edge_max(const int* __restrict__ ei,
                                                  const float* __restrict__ als,
                                                  const float* __restrict__ ald,
                                                  unsigned* __restrict__ emax) {
    int e = blockIdx.x * 256 + threadIdx.x;
    if (e >= ET) return;
    int s, d;
    if (!edge_sd(ei, e, s, d)) return;
    float4 s0 = *(const float4*)(als + s * 8);
    float4 s1 = *(const float4*)(als + s * 8 + 4);
    float4 d0 = *(const float4*)(ald + d * 8);
    float4 d1 = *(const float4*)(ald + d * 8 + 4);
    float sv[8] = {s0.x, s0.y, s0.z, s0.w, s1.x, s1.y, s1.z, s1.w};
    float dv[8] = {d0.x, d0.y, d0.z, d0.w, d1.x, d1.y, d1.z, d1.w};
    unsigned* em = emax + d * 8;
#pragma unroll
    for (int h = 0; h < 8; h++) {
        float v = sv[h] + dv[h];
        v = v > 0.f ? v : 0.2f * v;   // leaky_relu
        atomicMax(em + h, fkey(v));
    }
}

// ---------------- edge pass B: exp + denom, store e_exp ----------------
__global__ __launch_bounds__(256) void k_edge_expden(const int* __restrict__ ei,
                                                     const float* __restrict__ als,
                                                     const float* __restrict__ ald,
                                                     const unsigned* __restrict__ emax,
                                                     float* __restrict__ den,
                                                     float* __restrict__ eexp) {
    int e = blockIdx.x * 256 + threadIdx.x;
    if (e >= ET) return;
    int s, d;
    if (!edge_sd(ei, e, s, d)) return;
    float4 s0 = *(const float4*)(als + s * 8);
    float4 s1 = *(const float4*)(als + s * 8 + 4);
    float4 d0 = *(const float4*)(ald + d * 8);
    float4 d1 = *(const float4*)(ald + d * 8 + 4);
    float sv[8] = {s0.x, s0.y, s0.z, s0.w, s1.x, s1.y, s1.z, s1.w};
    float dv[8] = {d0.x, d0.y, d0.z, d0.w, d1.x, d1.y, d1.z, d1.w};
    float ee[8];
#pragma unroll
    for (int h = 0; h < 8; h++) {
        float v = sv[h] + dv[h];
        v = v > 0.f ? v : 0.2f * v;
        float m = funkey(__ldg(emax + d * 8 + h));
        ee[h] = __expf(v - m);
    }
    red4(den + d * 8,     ee[0], ee[1], ee[2], ee[3]);
    red4(den + d * 8 + 4, ee[4], ee[5], ee[6], ee[7]);
    *(float4*)(eexp + (size_t)e * 8)     = make_float4(ee[0], ee[1], ee[2], ee[3]);
    *(float4*)(eexp + (size_t)e * 8 + 4) = make_float4(ee[4], ee[5], ee[6], ee[7]);
}

// ---------------- edge pass C: alpha + weighted aggregation ----------------
// eexp is read-modify: alpha overwrites e_exp in place (same scratch buffer).
template <int D, bool WRITE_ALPHA>
__global__ __launch_bounds__(256) void k_edge_agg(const int* __restrict__ ei,
                                                  float* __restrict__ eexp,
                                                  const float* __restrict__ den,
                                                  const float* __restrict__ xw,
                                                  float* __restrict__ hacc) {
    int t = blockIdx.x * 256 + threadIdx.x;
    if (t >= ET * 8) return;
    int e = t >> 3, h = t & 7;
    int s, d;
    if (!edge_sd(ei, e, s, d)) return;
    float alpha = eexp[t] / (__ldg(den + d * 8 + h) + 1e-16f);
    if (WRITE_ALPHA) eexp[t] = alpha;     // in-place: becomes alpha1 scratch
    const float4* xs = (const float4*)(xw + (size_t)s * 8 * D + h * D);
    float* dp = hacc + (size_t)d * 8 * D + h * D;
#pragma unroll
    for (int j = 0; j < D / 4; j++) {
        float4 m = __ldg(xs + j);
        red4(dp + 4 * j, m.x * alpha, m.y * alpha, m.z * alpha, m.w * alpha);
    }
}

// ---------------- final: h2 + b2, log_softmax over 128 ----------------
__global__ __launch_bounds__(256) void k_logsoftmax(const float* __restrict__ h2,
                                                    const float* __restrict__ b2,
                                                    float* __restrict__ out) {
    int gw = (blockIdx.x * 256 + threadIdx.x) >> 5;
    int lane = threadIdx.x & 31;
    if (gw >= NN) return;
    const float* row = h2 + (size_t)gw * 128;
    float v[4];
#pragma unroll
    for (int i = 0; i < 4; i++) v[i] = row[lane + 32 * i] + __ldg(b2 + lane + 32 * i);
    float mx = fmaxf(fmaxf(v[0], v[1]), fmaxf(v[2], v[3]));
#pragma unroll
    for (int o = 16; o > 0; o >>= 1) mx = fmaxf(mx, __shfl_xor_sync(0xffffffffu, mx, o));
    float se = 0.f;
#pragma unroll
    for (int i = 0; i < 4; i++) se += __expf(v[i] - mx);
#pragma unroll
    for (int o = 16; o > 0; o >>= 1) se += __shfl_xor_sync(0xffffffffu, se, o);
    float ls = __logf(se);
    float* orow = out + (size_t)gw * 128;
#pragma unroll
    for (int i = 0; i < 4; i++) orow[lane + 32 * i] = v[i] - mx - ls;
}

// ---------------- launch ----------------
extern "C" void kernel_launch(void* const* d_in, const int* in_sizes, int n_in,
                              void* d_out, int out_size) {
    const float* x   = (const float*)d_in[0];
    const int*   ei  = (const int*)d_in[1];      // int32 (JAX x64 disabled)
    const float* W1  = (const float*)d_in[2];
    const float* a1s = (const float*)d_in[3];
    const float* a1d = (const float*)d_in[4];
    const float* b1  = (const float*)d_in[5];
    const float* W2  = (const float*)d_in[6];
    const float* a2s = (const float*)d_in[7];
    const float* a2d = (const float*)d_in[8];
    const float* b2  = (const float*)d_in[9];

    float* out = (float*)d_out;

    float *xw1, *als1, *ald1, *den1, *h1, *xw2, *als2, *ald2, *den2, *h2, *alpha1, *eexp2;
    unsigned *emax1, *emax2;
    cudaGetSymbolAddress((void**)&xw1,    g_xw1);
    cudaGetSymbolAddress((void**)&als1,   g_als1);
    cudaGetSymbolAddress((void**)&ald1,   g_ald1);
    cudaGetSymbolAddress((void**)&emax1,  g_emax1);
    cudaGetSymbolAddress((void**)&den1,   g_den1);
    cudaGetSymbolAddress((void**)&h1,     g_h1);
    cudaGetSymbolAddress((void**)&xw2,    g_xw2);
    cudaGetSymbolAddress((void**)&als2,   g_als2);
    cudaGetSymbolAddress((void**)&ald2,   g_ald2);
    cudaGetSymbolAddress((void**)&emax2,  g_emax2);
    cudaGetSymbolAddress((void**)&den2,   g_den2);
    cudaGetSymbolAddress((void**)&h2,     g_h2);
    cudaGetSymbolAddress((void**)&alpha1, g_alpha1);
    cudaGetSymbolAddress((void**)&eexp2,  g_eexp2);

    cudaMemsetAsync(emax1, 0, (size_t)NN * 8 * 4);
    cudaMemsetAsync(den1,  0, (size_t)NN * 8 * 4);
    cudaMemsetAsync(h1,    0, (size_t)NN * 64 * 4);
    cudaMemsetAsync(emax2, 0, (size_t)NN * 8 * 4);
    cudaMemsetAsync(den2,  0, (size_t)NN * 8 * 4);
    cudaMemsetAsync(h2,    0, (size_t)NN * 128 * 4);

    const int gemm_grid  = (NN + 63) / 64;          // 782
    const int attn_grid  = (NN * 8 + 255) / 256;
    const int edge_grid  = (ET + 255) / 256;
    const int agg_grid   = (ET * 8 + 255) / 256;    // note: 6.8M threads
    const int lsm_grid   = (NN * 32 + 255) / 256;

    // Layer 1
    k_gemm1<<<gemm_grid, 256>>>(x, W1, xw1);
    k_attn<8><<<attn_grid, 256>>>(xw1, a1s, a1d, als1, ald1);
    k_edge_max<<<edge_grid, 256>>>(ei, als1, ald1, emax1);
    k_edge_expden<<<edge_grid, 256>>>(ei, als1, ald1, emax1, den1, alpha1);
    k_edge_agg<8, true><<<agg_grid, 256>>>(ei, alpha1, den1, xw1, h1);

    // Layer 2
    k_gemm2<<<gemm_grid, 256>>>(h1, b1, W2, xw2);
    k_attn<16><<<attn_grid, 256>>>(xw2, a2s, a2d, als2, ald2);
    k_edge_max<<<edge_grid, 256>>>(ei, als2, ald2, emax2);
    k_edge_expden<<<edge_grid, 256>>>(ei, als2, ald2, emax2, den2, eexp2);
    k_edge_agg<16, false><<<agg_grid, 256>>>(ei, eexp2, den2, xw2, h2);

    // Outputs: logp always; alpha1 only if the out buffer actually has room for it.
    if (out_size >= NN * 128) {
        k_logsoftmax<<<lsm_grid, 256>>>(h2, b2, out);
    }
    if ((size_t)out_size >= (size_t)NN * 128 + (size_t)ET * 8) {
        cudaMemcpyAsync(out + (size_t)NN * 128, alpha1, (size_t)ET * 8 * 4,
                        cudaMemcpyDeviceToDevice);
    }
}

// round 5
// speedup vs baseline: 1.2043x; 1.2043x over previous
#include <cuda_runtime.h>

#define NN 50000
#define E0 800000
#define ET 850000

// ---------------- scratch (static device globals; no allocation) ----------------
__device__ float g_xw1[NN * 64];
__device__ float g_als1[NN * 8];
__device__ float g_ald1[NN * 8];
__device__ float g_den1[NN * 8];
__device__ float g_h1[NN * 64];      // unnormalized Σ ee*xw1
__device__ float g_xw2[NN * 128];
__device__ float g_als2[NN * 8];
__device__ float g_ald2[NN * 8];
__device__ float g_den2[NN * 8];
__device__ float g_h2[NN * 128];     // unnormalized Σ ee*xw2
__device__ float g_ee1[(size_t)ET * 8];  // layer-1 e_exp (for alpha output)

// ---------------- helpers ----------------
__device__ __forceinline__ void red4(float* p, float a, float b, float c, float d) {
    asm volatile("red.global.add.v4.f32 [%0], {%1,%2,%3,%4};"
                 :: "l"(p), "f"(a), "f"(b), "f"(c), "f"(d) : "memory");
}
__device__ __forceinline__ void red1(float* p, float a) {
    asm volatile("red.global.add.f32 [%0], %1;" :: "l"(p), "f"(a) : "memory");
}
// edge_index is int32
__device__ __forceinline__ bool edge_sd(const int* __restrict__ ei, int e, int& s, int& d) {
    if (e < E0) { s = __ldg(ei + e); d = __ldg(ei + E0 + e); }
    else        { s = e - E0; d = s; }
    return ((unsigned)s < NN) && ((unsigned)d < NN);
}

// ---------------- GEMM1: x[NN,256] @ W1[256,64] -> g_xw1 ----------------
__global__ __launch_bounds__(256) void k_gemm1(const float* __restrict__ A,
                                               const float* __restrict__ B,
                                               float* __restrict__ C) {
    __shared__ float As[32][68];
    __shared__ float Bs[32][68];
    int tid = threadIdx.x;
    int tx = tid & 15, ty = tid >> 4;
    int bm = blockIdx.x * 64;
    float acc[4][4] = {};
    for (int k0 = 0; k0 < 256; k0 += 32) {
#pragma unroll
        for (int i = 0; i < 8; i++) {
            int idx = tid + i * 256;
            int m = idx >> 5, k = idx & 31;
            int row = bm + m;
            As[k][m] = (row < NN) ? A[row * 256 + k0 + k] : 0.f;
            int k2 = idx >> 6, n2 = idx & 63;
            Bs[k2][n2] = B[(k0 + k2) * 64 + n2];
        }
        __syncthreads();
#pragma unroll
        for (int k = 0; k < 32; k++) {
            float4 a4 = *(const float4*)&As[k][ty * 4];
            float4 b4 = *(const float4*)&Bs[k][tx * 4];
            float av[4] = {a4.x, a4.y, a4.z, a4.w};
            float bv[4] = {b4.x, b4.y, b4.z, b4.w};
#pragma unroll
            for (int i = 0; i < 4; i++)
#pragma unroll
                for (int j = 0; j < 4; j++) acc[i][j] += av[i] * bv[j];
        }
        __syncthreads();
    }
#pragma unroll
    for (int i = 0; i < 4; i++) {
        int row = bm + ty * 4 + i;
        if (row < NN)
            *(float4*)&C[row * 64 + tx * 4] =
                make_float4(acc[i][0], acc[i][1], acc[i][2], acc[i][3]);
    }
}

// ---------------- GEMM2: elu(hacc1/den1 + b1)[NN,64] @ W2[64,128] -> g_xw2 ----------------
__global__ __launch_bounds__(256) void k_gemm2(const float* __restrict__ A,     // g_h1 (unnormalized)
                                               const float* __restrict__ den1,
                                               const float* __restrict__ bias1,
                                               const float* __restrict__ B,
                                               float* __restrict__ C) {
    __shared__ float As[32][68];
    __shared__ float Bs[32][132];
    int tid = threadIdx.x;
    int tx = tid & 15, ty = tid >> 4;
    int bm = blockIdx.x * 64;
    float acc[4][8] = {};
    for (int k0 = 0; k0 < 64; k0 += 32) {
#pragma unroll
        for (int i = 0; i < 8; i++) {
            int idx = tid + i * 256;
            int m = idx >> 5, k = idx & 31;
            int row = bm + m;
            float v = 0.f;
            if (row < NN) {
                int kk = k0 + k;
                float dn = __ldg(den1 + row * 8 + (kk >> 3)) + 1e-16f;
                v = A[row * 64 + kk] / dn + bias1[kk];
                v = v > 0.f ? v : expm1f(v);           // ELU
            }
            As[k][m] = v;
        }
#pragma unroll
        for (int i = 0; i < 16; i++) {
            int idx = tid + i * 256;
            int k = idx >> 7, n = idx & 127;
            Bs[k][n] = B[(k0 + k) * 128 + n];
        }
        __syncthreads();
#pragma unroll
        for (int k = 0; k < 32; k++) {
            float4 a4  = *(const float4*)&As[k][ty * 4];
            float4 b40 = *(const float4*)&Bs[k][tx * 8];
            float4 b41 = *(const float4*)&Bs[k][tx * 8 + 4];
            float av[4] = {a4.x, a4.y, a4.z, a4.w};
            float bv[8] = {b40.x, b40.y, b40.z, b40.w, b41.x, b41.y, b41.z, b41.w};
#pragma unroll
            for (int i = 0; i < 4; i++)
#pragma unroll
                for (int j = 0; j < 8; j++) acc[i][j] += av[i] * bv[j];
        }
        __syncthreads();
    }
#pragma unroll
    for (int i = 0; i < 4; i++) {
        int row = bm + ty * 4 + i;
        if (row < NN) {
            *(float4*)&C[row * 128 + tx * 8]     = make_float4(acc[i][0], acc[i][1], acc[i][2], acc[i][3]);
            *(float4*)&C[row * 128 + tx * 8 + 4] = make_float4(acc[i][4], acc[i][5], acc[i][6], acc[i][7]);
        }
    }
}

// ---------------- attention logits ----------------
template <int D>
__global__ __launch_bounds__(256) void k_attn(const float* __restrict__ xw,
                                              const float* __restrict__ as_,
                                              const float* __restrict__ ad_,
                                              float* __restrict__ als,
                                              float* __restrict__ ald) {
    int t = blockIdx.x * 256 + threadIdx.x;
    if (t >= NN * 8) return;
    int n = t >> 3, h = t & 7;
    const float* row = xw + (size_t)n * 8 * D + h * D;
    float s = 0.f, d = 0.f;
#pragma unroll
    for (int i = 0; i < D; i++) {
        float v = __ldg(row + i);
        s += v * __ldg(as_ + h * D + i);
        d += v * __ldg(ad_ + h * D + i);
    }
    als[t] = s;
    ald[t] = d;
}

// ---------------- fused edge pass: exp + denom-red + weighted aggregation ----------------
// one thread per (edge, head). No segment-max: logits are O(10), fp32 exp is exact enough.
template <int D, bool STORE_EE>
__global__ __launch_bounds__(256) void k_edge_fused(const int* __restrict__ ei,
                                                    const float* __restrict__ als,
                                                    const float* __restrict__ ald,
                                                    const float* __restrict__ xw,
                                                    float* __restrict__ den,
                                                    float* __restrict__ hacc,
                                                    float* __restrict__ eeout) {
    int t = blockIdx.x * 256 + threadIdx.x;
    if (t >= ET * 8) return;
    int e = t >> 3, h = t & 7;
    int s, d;
    if (!edge_sd(ei, e, s, d)) return;
    float v = __ldg(als + s * 8 + h) + __ldg(ald + d * 8 + h);
    v = v > 0.f ? v : 0.2f * v;          // leaky_relu
    float ee = __expf(v);
    if (STORE_EE) eeout[t] = ee;
    red1(den + d * 8 + h, ee);
    const float4* xs = (const float4*)(xw + (size_t)s * 8 * D + h * D);
    float* dp = hacc + (size_t)d * 8 * D + h * D;
#pragma unroll
    for (int j = 0; j < D / 4; j++) {
        float4 m = __ldg(xs + j);
        red4(dp + 4 * j, ee * m.x, ee * m.y, ee * m.z, ee * m.w);
    }
}

// ---------------- layer-1 alpha: ee/den -> out ----------------
__global__ __launch_bounds__(256) void k_alpha(const int* __restrict__ ei,
                                               const float* __restrict__ ee,
                                               const float* __restrict__ den,
                                               float* __restrict__ aout) {
    int t = blockIdx.x * 256 + threadIdx.x;
    if (t >= ET * 8) return;
    int e = t >> 3, h = t & 7;
    int s, d;
    if (!edge_sd(ei, e, s, d)) return;
    aout[t] = ee[t] / (__ldg(den + d * 8 + h) + 1e-16f);
}

// ---------------- final: hacc2/den2 + b2, log_softmax over 128 ----------------
__global__ __launch_bounds__(256) void k_logsoftmax(const float* __restrict__ h2,
                                                    const float* __restrict__ den2,
                                                    const float* __restrict__ b2,
                                                    float* __restrict__ out) {
    int gw = (blockIdx.x * 256 + threadIdx.x) >> 5;
    int lane = threadIdx.x & 31;
    if (gw >= NN) return;
    const float* row = h2 + (size_t)gw * 128;
    float v[4];
#pragma unroll
    for (int i = 0; i < 4; i++) {
        int c = lane + 32 * i;
        float dn = __ldg(den2 + gw * 8 + (c >> 4)) + 1e-16f;
        v[i] = row[c] / dn + __ldg(b2 + c);
    }
    float mx = fmaxf(fmaxf(v[0], v[1]), fmaxf(v[2], v[3]));
#pragma unroll
    for (int o = 16; o > 0; o >>= 1) mx = fmaxf(mx, __shfl_xor_sync(0xffffffffu, mx, o));
    float se = 0.f;
#pragma unroll
    for (int i = 0; i < 4; i++) se += __expf(v[i] - mx);
#pragma unroll
    for (int o = 16; o > 0; o >>= 1) se += __shfl_xor_sync(0xffffffffu, se, o);
    float ls = __logf(se);
    float* orow = out + (size_t)gw * 128;
#pragma unroll
    for (int i = 0; i < 4; i++) orow[lane + 32 * i] = v[i] - mx - ls;
}

// ---------------- launch ----------------
extern "C" void kernel_launch(void* const* d_in, const int* in_sizes, int n_in,
                              void* d_out, int out_size) {
    const float* x   = (const float*)d_in[0];
    const int*   ei  = (const int*)d_in[1];
    const float* W1  = (const float*)d_in[2];
    const float* a1s = (const float*)d_in[3];
    const float* a1d = (const float*)d_in[4];
    const float* b1  = (const float*)d_in[5];
    const float* W2  = (const float*)d_in[6];
    const float* a2s = (const float*)d_in[7];
    const float* a2d = (const float*)d_in[8];
    const float* b2  = (const float*)d_in[9];

    float* out = (float*)d_out;

    float *xw1, *als1, *ald1, *den1, *h1, *xw2, *als2, *ald2, *den2, *h2, *ee1;
    cudaGetSymbolAddress((void**)&xw1,  g_xw1);
    cudaGetSymbolAddress((void**)&als1, g_als1);
    cudaGetSymbolAddress((void**)&ald1, g_ald1);
    cudaGetSymbolAddress((void**)&den1, g_den1);
    cudaGetSymbolAddress((void**)&h1,   g_h1);
    cudaGetSymbolAddress((void**)&xw2,  g_xw2);
    cudaGetSymbolAddress((void**)&als2, g_als2);
    cudaGetSymbolAddress((void**)&ald2, g_ald2);
    cudaGetSymbolAddress((void**)&den2, g_den2);
    cudaGetSymbolAddress((void**)&h2,   g_h2);
    cudaGetSymbolAddress((void**)&ee1,  g_ee1);

    cudaMemsetAsync(den1, 0, (size_t)NN * 8 * 4);
    cudaMemsetAsync(h1,   0, (size_t)NN * 64 * 4);
    cudaMemsetAsync(den2, 0, (size_t)NN * 8 * 4);
    cudaMemsetAsync(h2,   0, (size_t)NN * 128 * 4);

    const int gemm_grid = (NN + 63) / 64;
    const int attn_grid = (NN * 8 + 255) / 256;
    const int eh_grid   = (ET * 8 + 255) / 256;
    const int lsm_grid  = (NN * 32 + 255) / 256;

    // Layer 1
    k_gemm1<<<gemm_grid, 256>>>(x, W1, xw1);
    k_attn<8><<<attn_grid, 256>>>(xw1, a1s, a1d, als1, ald1);
    k_edge_fused<8, true><<<eh_grid, 256>>>(ei, als1, ald1, xw1, den1, h1, ee1);

    // Layer 2 (division by den1 + bias + ELU folded into gemm2's A-load)
    k_gemm2<<<gemm_grid, 256>>>(h1, den1, b1, W2, xw2);
    k_attn<16><<<attn_grid, 256>>>(xw2, a2s, a2d, als2, ald2);
    k_edge_fused<16, false><<<eh_grid, 256>>>(ei, als2, ald2, xw2, den2, h2, nullptr);

    // Outputs
    if (out_size >= NN * 128) {
        k_logsoftmax<<<lsm_grid, 256>>>(h2, den2, b2, out);
    }
    if ((size_t)out_size >= (size_t)NN * 128 + (size_t)ET * 8) {
        k_alpha<<<eh_grid, 256>>>(ei, ee1, den1, out + (size_t)NN * 128);
    }
}

// round 9
// speedup vs baseline: 1.3675x; 1.1355x over previous
#include <cuda_runtime.h>

#define NN 50000
#define E0 800000
#define ET 850000

// ---------------- scratch (static device globals; no allocation) ----------------
__device__ float g_xw1[NN * 64];
__device__ float g_als1[NN * 8];
__device__ float g_ald1[NN * 8];
__device__ float g_den1[NN * 8];
__device__ float g_h1[NN * 64];      // unnormalized Σ ee*xw1
__device__ float g_h1n[NN * 64];     // elu(h1/den1 + b1)
__device__ float g_xw2[NN * 128];
__device__ float g_als2[NN * 8];
__device__ float g_ald2[NN * 8];
__device__ float g_den2[NN * 8];
__device__ float g_h2[NN * 128];     // unnormalized Σ ee*xw2
__device__ float g_ee1[(size_t)ET * 8];  // layer-1 e_exp (for alpha output)

// ---------------- helpers ----------------
__device__ __forceinline__ void red4(float* p, float a, float b, float c, float d) {
    asm volatile("red.global.add.v4.f32 [%0], {%1,%2,%3,%4};"
                 :: "l"(p), "f"(a), "f"(b), "f"(c), "f"(d) : "memory");
}
__device__ __forceinline__ void red1(float* p, float a) {
    asm volatile("red.global.add.f32 [%0], %1;" :: "l"(p), "f"(a) : "memory");
}
__device__ __forceinline__ bool edge_sd(const int* __restrict__ ei, int e, int& s, int& d) {
    if (e < E0) { s = __ldg(ei + e); d = __ldg(ei + E0 + e); }
    else        { s = e - E0; d = s; }
    return ((unsigned)s < NN) && ((unsigned)d < NN);
}

// ---------------- GEMM1: x[NN,256] @ W1[256,64] -> g_xw1 ----------------
// 128x64 block tile, BK=32, 8x4 micro-tile, 256 threads
__global__ __launch_bounds__(256) void k_gemm1(const float* __restrict__ A,
                                               const float* __restrict__ B,
                                               float* __restrict__ C) {
    __shared__ float As[32][132];
    __shared__ float Bs[32][68];
    int tid = threadIdx.x;
    int tx = tid & 15, ty = tid >> 4;
    int bm = blockIdx.x * 128;
    float acc[8][4] = {};
    for (int k0 = 0; k0 < 256; k0 += 32) {
        // A tile: 128 rows x 32 k = 1024 float4
#pragma unroll
        for (int i = 0; i < 4; i++) {
            int f = tid + i * 256;
            int row = f >> 3, kq = f & 7;
            int gr = bm + row;
            float4 v = (gr < NN) ? *(const float4*)&A[(size_t)gr * 256 + k0 + kq * 4]
                                 : make_float4(0.f, 0.f, 0.f, 0.f);
            As[kq * 4 + 0][row] = v.x;
            As[kq * 4 + 1][row] = v.y;
            As[kq * 4 + 2][row] = v.z;
            As[kq * 4 + 3][row] = v.w;
        }
        // B tile: 32 k x 64 n = 512 float4
#pragma unroll
        for (int i = 0; i < 2; i++) {
            int f = tid + i * 256;
            int k = f >> 4, nq = f & 15;
            *(float4*)&Bs[k][nq * 4] = *(const float4*)&B[(size_t)(k0 + k) * 64 + nq * 4];
        }
        __syncthreads();
#pragma unroll
        for (int k = 0; k < 32; k++) {
            float4 a0 = *(const float4*)&As[k][ty * 8];
            float4 a1 = *(const float4*)&As[k][ty * 8 + 4];
            float4 b0 = *(const float4*)&Bs[k][tx * 4];
            float av[8] = {a0.x, a0.y, a0.z, a0.w, a1.x, a1.y, a1.z, a1.w};
            float bv[4] = {b0.x, b0.y, b0.z, b0.w};
#pragma unroll
            for (int i = 0; i < 8; i++)
#pragma unroll
                for (int j = 0; j < 4; j++) acc[i][j] += av[i] * bv[j];
        }
        __syncthreads();
    }
#pragma unroll
    for (int i = 0; i < 8; i++) {
        int row = bm + ty * 8 + i;
        if (row < NN)
            *(float4*)&C[(size_t)row * 64 + tx * 4] =
                make_float4(acc[i][0], acc[i][1], acc[i][2], acc[i][3]);
    }
}

// ---------------- norm+ELU: h1n = elu(h1/den1 + b1) ----------------
__global__ __launch_bounds__(256) void k_norm_elu(const float* __restrict__ h1,
                                                  const float* __restrict__ den1,
                                                  const float* __restrict__ b1,
                                                  float* __restrict__ h1n) {
    int t4 = blockIdx.x * 256 + threadIdx.x;
    if (t4 >= NN * 16) return;                 // NN*64/4 float4s
    int c = t4 * 4;
    int row = c >> 6, col = c & 63;
    float dn = __ldg(den1 + row * 8 + (col >> 3)) + 1e-16f;
    float inv = 1.0f / dn;
    float4 a = *(const float4*)(h1 + c);
    float4 b = *(const float4*)(b1 + col);
    float v[4] = {a.x * inv + b.x, a.y * inv + b.y, a.z * inv + b.z, a.w * inv + b.w};
#pragma unroll
    for (int j = 0; j < 4; j++) v[j] = v[j] > 0.f ? v[j] : (__expf(v[j]) - 1.f);
    *(float4*)(h1n + c) = make_float4(v[0], v[1], v[2], v[3]);
}

// ---------------- GEMM2: h1n[NN,64] @ W2[64,128] -> g_xw2 ----------------
// 128x128 block tile, BK=16, 8x8 micro-tile, 256 threads
__global__ __launch_bounds__(256) void k_gemm2(const float* __restrict__ A,
                                               const float* __restrict__ B,
                                               float* __restrict__ C) {
    __shared__ float As[16][132];
    __shared__ float Bs[16][132];
    int tid = threadIdx.x;
    int tx = tid & 15, ty = tid >> 4;
    int bm = blockIdx.x * 128;
    float acc[8][8] = {};
    for (int k0 = 0; k0 < 64; k0 += 16) {
        // A tile: 128 rows x 16 k = 512 float4
#pragma unroll
        for (int i = 0; i < 2; i++) {
            int f = tid + i * 256;
            int row = f >> 2, kq = f & 3;
            int gr = bm + row;
            float4 v = (gr < NN) ? *(const float4*)&A[(size_t)gr * 64 + k0 + kq * 4]
                                 : make_float4(0.f, 0.f, 0.f, 0.f);
            As[kq * 4 + 0][row] = v.x;
            As[kq * 4 + 1][row] = v.y;
            As[kq * 4 + 2][row] = v.z;
            As[kq * 4 + 3][row] = v.w;
        }
        // B tile: 16 k x 128 n = 512 float4
#pragma unroll
        for (int i = 0; i < 2; i++) {
            int f = tid + i * 256;
            int k = f >> 5, nq = f & 31;
            *(float4*)&Bs[k][nq * 4] = *(const float4*)&B[(size_t)(k0 + k) * 128 + nq * 4];
        }
        __syncthreads();
#pragma unroll
        for (int k = 0; k < 16; k++) {
            float4 a0 = *(const float4*)&As[k][ty * 8];
            float4 a1 = *(const float4*)&As[k][ty * 8 + 4];
            float4 b0 = *(const float4*)&Bs[k][tx * 8];
            float4 b1 = *(const float4*)&Bs[k][tx * 8 + 4];
            float av[8] = {a0.x, a0.y, a0.z, a0.w, a1.x, a1.y, a1.z, a1.w};
            float bv[8] = {b0.x, b0.y, b0.z, b0.w, b1.x, b1.y, b1.z, b1.w};
#pragma unroll
            for (int i = 0; i < 8; i++)
#pragma unroll
                for (int j = 0; j < 8; j++) acc[i][j] += av[i] * bv[j];
        }
        __syncthreads();
    }
#pragma unroll
    for (int i = 0; i < 8; i++) {
        int row = bm + ty * 8 + i;
        if (row < NN) {
            *(float4*)&C[(size_t)row * 128 + tx * 8]     = make_float4(acc[i][0], acc[i][1], acc[i][2], acc[i][3]);
            *(float4*)&C[(size_t)row * 128 + tx * 8 + 4] = make_float4(acc[i][4], acc[i][5], acc[i][6], acc[i][7]);
        }
    }
}

// ---------------- attention logits ----------------
template <int D>
__global__ __launch_bounds__(256) void k_attn(const float* __restrict__ xw,
                                              const float* __restrict__ as_,
                                              const float* __restrict__ ad_,
                                              float* __restrict__ als,
                                              float* __restrict__ ald) {
    int t = blockIdx.x * 256 + threadIdx.x;
    if (t >= NN * 8) return;
    int n = t >> 3, h = t & 7;
    const float* row = xw + (size_t)n * 8 * D + h * D;
    float s = 0.f, d = 0.f;
#pragma unroll
    for (int i = 0; i < D; i++) {
        float v = __ldg(row + i);
        s += v * __ldg(as_ + h * D + i);
        d += v * __ldg(ad_ + h * D + i);
    }
    als[t] = s;
    ald[t] = d;
}

// ---------------- fused edge pass: exp + denom-red + weighted aggregation ----------------
template <int D, bool STORE_EE>
__global__ __launch_bounds__(256) void k_edge_fused(const int* __restrict__ ei,
                                                    const float* __restrict__ als,
                                                    const float* __restrict__ ald,
                                                    const float* __restrict__ xw,
                                                    float* __restrict__ den,
                                                    float* __restrict__ hacc,
                                                    float* __restrict__ eeout) {
    int t = blockIdx.x * 256 + threadIdx.x;
    if (t >= ET * 8) return;
    int e = t >> 3, h = t & 7;
    int s, d;
    if (!edge_sd(ei, e, s, d)) return;
    float v = __ldg(als + s * 8 + h) + __ldg(ald + d * 8 + h);
    v = v > 0.f ? v : 0.2f * v;          // leaky_relu
    float ee = __expf(v);
    if (STORE_EE) eeout[t] = ee;
    red1(den + d * 8 + h, ee);
    const float4* xs = (const float4*)(xw + (size_t)s * 8 * D + h * D);
    float* dp = hacc + (size_t)d * 8 * D + h * D;
#pragma unroll
    for (int j = 0; j < D / 4; j++) {
        float4 m = __ldg(xs + j);
        red4(dp + 4 * j, ee * m.x, ee * m.y, ee * m.z, ee * m.w);
    }
}

// ---------------- layer-1 alpha: ee/den -> out ----------------
__global__ __launch_bounds__(256) void k_alpha(const int* __restrict__ ei,
                                               const float* __restrict__ ee,
                                               const float* __restrict__ den,
                                               float* __restrict__ aout) {
    int t = blockIdx.x * 256 + threadIdx.x;
    if (t >= ET * 8) return;
    int e = t >> 3, h = t & 7;
    int d;
    if (e < E0) d = __ldg(ei + E0 + e);
    else        d = e - E0;
    if ((unsigned)d >= NN) return;
    aout[t] = ee[t] / (__ldg(den + d * 8 + h) + 1e-16f);
}

// ---------------- final: hacc2/den2 + b2, log_softmax over 128 ----------------
__global__ __launch_bounds__(256) void k_logsoftmax(const float* __restrict__ h2,
                                                    const float* __restrict__ den2,
                                                    const float* __restrict__ b2,
                                                    float* __restrict__ out) {
    int gw = (blockIdx.x * 256 + threadIdx.x) >> 5;
    int lane = threadIdx.x & 31;
    if (gw >= NN) return;
    const float* row = h2 + (size_t)gw * 128;
    float v[4];
#pragma unroll
    for (int i = 0; i < 4; i++) {
        int c = lane + 32 * i;
        float dn = __ldg(den2 + gw * 8 + (c >> 4)) + 1e-16f;
        v[i] = row[c] / dn + __ldg(b2 + c);
    }
    float mx = fmaxf(fmaxf(v[0], v[1]), fmaxf(v[2], v[3]));
#pragma unroll
    for (int o = 16; o > 0; o >>= 1) mx = fmaxf(mx, __shfl_xor_sync(0xffffffffu, mx, o));
    float se = 0.f;
#pragma unroll
    for (int i = 0; i < 4; i++) se += __expf(v[i] - mx);
#pragma unroll
    for (int o = 16; o > 0; o >>= 1) se += __shfl_xor_sync(0xffffffffu, se, o);
    float ls = __logf(se);
    float* orow = out + (size_t)gw * 128;
#pragma unroll
    for (int i = 0; i < 4; i++) orow[lane + 32 * i] = v[i] - mx - ls;
}

// ---------------- launch ----------------
extern "C" void kernel_launch(void* const* d_in, const int* in_sizes, int n_in,
                              void* d_out, int out_size) {
    const float* x   = (const float*)d_in[0];
    const int*   ei  = (const int*)d_in[1];
    const float* W1  = (const float*)d_in[2];
    const float* a1s = (const float*)d_in[3];
    const float* a1d = (const float*)d_in[4];
    const float* b1  = (const float*)d_in[5];
    const float* W2  = (const float*)d_in[6];
    const float* a2s = (const float*)d_in[7];
    const float* a2d = (const float*)d_in[8];
    const float* b2  = (const float*)d_in[9];

    float* out = (float*)d_out;

    float *xw1, *als1, *ald1, *den1, *h1, *h1n, *xw2, *als2, *ald2, *den2, *h2, *ee1;
    cudaGetSymbolAddress((void**)&xw1,  g_xw1);
    cudaGetSymbolAddress((void**)&als1, g_als1);
    cudaGetSymbolAddress((void**)&ald1, g_ald1);
    cudaGetSymbolAddress((void**)&den1, g_den1);
    cudaGetSymbolAddress((void**)&h1,   g_h1);
    cudaGetSymbolAddress((void**)&h1n,  g_h1n);
    cudaGetSymbolAddress((void**)&xw2,  g_xw2);
    cudaGetSymbolAddress((void**)&als2, g_als2);
    cudaGetSymbolAddress((void**)&ald2, g_ald2);
    cudaGetSymbolAddress((void**)&den2, g_den2);
    cudaGetSymbolAddress((void**)&h2,   g_h2);
    cudaGetSymbolAddress((void**)&ee1,  g_ee1);

    cudaMemsetAsync(den1, 0, (size_t)NN * 8 * 4);
    cudaMemsetAsync(h1,   0, (size_t)NN * 64 * 4);
    cudaMemsetAsync(den2, 0, (size_t)NN * 8 * 4);
    cudaMemsetAsync(h2,   0, (size_t)NN * 128 * 4);

    const int gemm_grid = (NN + 127) / 128;          // 391
    const int attn_grid = (NN * 8 + 255) / 256;
    const int eh_grid   = (ET * 8 + 255) / 256;
    const int ne_grid   = (NN * 16 + 255) / 256;
    const int lsm_grid  = (NN * 32 + 255) / 256;

    // Layer 1
    k_gemm1<<<gemm_grid, 256>>>(x, W1, xw1);
    k_attn<8><<<attn_grid, 256>>>(xw1, a1s, a1d, als1, ald1);
    k_edge_fused<8, true><<<eh_grid, 256>>>(ei, als1, ald1, xw1, den1, h1, ee1);

    // Layer 2
    k_norm_elu<<<ne_grid, 256>>>(h1, den1, b1, h1n);
    k_gemm2<<<gemm_grid, 256>>>(h1n, W2, xw2);
    k_attn<16><<<attn_grid, 256>>>(xw2, a2s, a2d, als2, ald2);
    k_edge_fused<16, false><<<eh_grid, 256>>>(ei, als2, ald2, xw2, den2, h2, nullptr);

    // Outputs
    if (out_size >= NN * 128) {
        k_logsoftmax<<<lsm_grid, 256>>>(h2, den2, b2, out);
    }
    if ((size_t)out_size >= (size_t)NN * 128 + (size_t)ET * 8) {
        k_alpha<<<eh_grid, 256>>>(ei, ee1, den1, out + (size_t)NN * 128);
    }
}

// round 12
// speedup vs baseline: 1.8050x; 1.3199x over previous
#include <cuda_runtime.h>

#define NN 50000
#define E0 800000
#define ET 850000

// ---------------- scratch (static device globals; no allocation) ----------------
__device__ float g_xw1[NN * 64];
__device__ float g_als1[NN * 8];
__device__ float g_ald1[NN * 8];
__device__ float g_h1n[NN * 64];     // elu(agg1/den + b1)
__device__ float g_xw2[NN * 128];
__device__ float g_als2[NN * 8];
__device__ float g_ald2[NN * 8];
__device__ int   g_cnt[NN];
__device__ int   g_off[NN + 1];
__device__ int   g_cur[NN];
__device__ int2  g_csr[ET];          // (src, edge_id) grouped by dst

// ---------------- CSR build ----------------
__global__ __launch_bounds__(256) void k_hist(const int* __restrict__ ei,
                                              int* __restrict__ cnt) {
    int e = blockIdx.x * 256 + threadIdx.x;
    if (e >= ET) return;
    int d = (e < E0) ? __ldg(ei + E0 + e) : (e - E0);
    if ((unsigned)d >= NN) return;
    atomicAdd(cnt + d, 1);
}

// single block, 1024 threads: exclusive scan of g_cnt -> g_off (+g_cur copy)
__global__ __launch_bounds__(1024) void k_scan(const int* __restrict__ cnt,
                                               int* __restrict__ off,
                                               int* __restrict__ cur) {
    const int PER = (NN + 1023) / 1024;   // 49
    int t = threadIdx.x;
    int base = t * PER;
    int sum = 0;
    for (int i = 0; i < PER; i++) {
        int idx = base + i;
        if (idx < NN) sum += __ldg(cnt + idx);
    }
    int lane = t & 31, wid = t >> 5;
    int v = sum;
#pragma unroll
    for (int o = 1; o < 32; o <<= 1) {
        int n = __shfl_up_sync(0xffffffffu, v, o);
        if (lane >= o) v += n;
    }
    __shared__ int ws[32];
    if (lane == 31) ws[wid] = v;
    __syncthreads();
    if (wid == 0) {
        int w = ws[lane];
#pragma unroll
        for (int o = 1; o < 32; o <<= 1) {
            int n = __shfl_up_sync(0xffffffffu, w, o);
            if (lane >= o) w += n;
        }
        ws[lane] = w;
    }
    __syncthreads();
    int run = v - sum + (wid > 0 ? ws[wid - 1] : 0);   // exclusive prefix
    for (int i = 0; i < PER; i++) {
        int idx = base + i;
        if (idx < NN) {
            off[idx] = run;
            cur[idx] = run;
            run += __ldg(cnt + idx);
        }
    }
    if (t == 1023) off[NN] = run;
}

__global__ __launch_bounds__(256) void k_scatter(const int* __restrict__ ei,
                                                 int* __restrict__ cur,
                                                 int2* __restrict__ csr) {
    int e = blockIdx.x * 256 + threadIdx.x;
    if (e >= ET) return;
    int s, d;
    if (e < E0) { s = __ldg(ei + e); d = __ldg(ei + E0 + e); }
    else        { s = e - E0; d = s; }
    if ((unsigned)s >= NN || (unsigned)d >= NN) return;
    int pos = atomicAdd(cur + d, 1);
    csr[pos] = make_int2(s, e);
}

// ---------------- GEMM1: x[NN,256] @ W1[256,64] -> g_xw1 ----------------
__global__ __launch_bounds__(256) void k_gemm1(const float* __restrict__ A,
                                               const float* __restrict__ B,
                                               float* __restrict__ C) {
    __shared__ float As[32][132];
    __shared__ float Bs[32][68];
    int tid = threadIdx.x;
    int tx = tid & 15, ty = tid >> 4;
    int bm = blockIdx.x * 128;
    float acc[8][4] = {};
    for (int k0 = 0; k0 < 256; k0 += 32) {
#pragma unroll
        for (int i = 0; i < 4; i++) {
            int f = tid + i * 256;
            int row = f >> 3, kq = f & 7;
            int gr = bm + row;
            float4 v = (gr < NN) ? *(const float4*)&A[(size_t)gr * 256 + k0 + kq * 4]
                                 : make_float4(0.f, 0.f, 0.f, 0.f);
            As[kq * 4 + 0][row] = v.x;
            As[kq * 4 + 1][row] = v.y;
            As[kq * 4 + 2][row] = v.z;
            As[kq * 4 + 3][row] = v.w;
        }
#pragma unroll
        for (int i = 0; i < 2; i++) {
            int f = tid + i * 256;
            int k = f >> 4, nq = f & 15;
            *(float4*)&Bs[k][nq * 4] = *(const float4*)&B[(size_t)(k0 + k) * 64 + nq * 4];
        }
        __syncthreads();
#pragma unroll
        for (int k = 0; k < 32; k++) {
            float4 a0 = *(const float4*)&As[k][ty * 8];
            float4 a1 = *(const float4*)&As[k][ty * 8 + 4];
            float4 b0 = *(const float4*)&Bs[k][tx * 4];
            float av[8] = {a0.x, a0.y, a0.z, a0.w, a1.x, a1.y, a1.z, a1.w};
            float bv[4] = {b0.x, b0.y, b0.z, b0.w};
#pragma unroll
            for (int i = 0; i < 8; i++)
#pragma unroll
                for (int j = 0; j < 4; j++) acc[i][j] += av[i] * bv[j];
        }
        __syncthreads();
    }
#pragma unroll
    for (int i = 0; i < 8; i++) {
        int row = bm + ty * 8 + i;
        if (row < NN)
            *(float4*)&C[(size_t)row * 64 + tx * 4] =
                make_float4(acc[i][0], acc[i][1], acc[i][2], acc[i][3]);
    }
}

// ---------------- GEMM2: h1n[NN,64] @ W2[64,128] -> g_xw2 ----------------
__global__ __launch_bounds__(256) void k_gemm2(const float* __restrict__ A,
                                               const float* __restrict__ B,
                                               float* __restrict__ C) {
    __shared__ float As[16][132];
    __shared__ float Bs[16][132];
    int tid = threadIdx.x;
    int tx = tid & 15, ty = tid >> 4;
    int bm = blockIdx.x * 128;
    float acc[8][8] = {};
    for (int k0 = 0; k0 < 64; k0 += 16) {
#pragma unroll
        for (int i = 0; i < 2; i++) {
            int f = tid + i * 256;
            int row = f >> 2, kq = f & 3;
            int gr = bm + row;
            float4 v = (gr < NN) ? *(const float4*)&A[(size_t)gr * 64 + k0 + kq * 4]
                                 : make_float4(0.f, 0.f, 0.f, 0.f);
            As[kq * 4 + 0][row] = v.x;
            As[kq * 4 + 1][row] = v.y;
            As[kq * 4 + 2][row] = v.z;
            As[kq * 4 + 3][row] = v.w;
        }
#pragma unroll
        for (int i = 0; i < 2; i++) {
            int f = tid + i * 256;
            int k = f >> 5, nq = f & 31;
            *(float4*)&Bs[k][nq * 4] = *(const float4*)&B[(size_t)(k0 + k) * 128 + nq * 4];
        }
        __syncthreads();
#pragma unroll
        for (int k = 0; k < 16; k++) {
            float4 a0 = *(const float4*)&As[k][ty * 8];
            float4 a1 = *(const float4*)&As[k][ty * 8 + 4];
            float4 b0 = *(const float4*)&Bs[k][tx * 8];
            float4 b1 = *(const float4*)&Bs[k][tx * 8 + 4];
            float av[8] = {a0.x, a0.y, a0.z, a0.w, a1.x, a1.y, a1.z, a1.w};
            float bv[8] = {b0.x, b0.y, b0.z, b0.w, b1.x, b1.y, b1.z, b1.w};
#pragma unroll
            for (int i = 0; i < 8; i++)
#pragma unroll
                for (int j = 0; j < 8; j++) acc[i][j] += av[i] * bv[j];
        }
        __syncthreads();
    }
#pragma unroll
    for (int i = 0; i < 8; i++) {
        int row = bm + ty * 8 + i;
        if (row < NN) {
            *(float4*)&C[(size_t)row * 128 + tx * 8]     = make_float4(acc[i][0], acc[i][1], acc[i][2], acc[i][3]);
            *(float4*)&C[(size_t)row * 128 + tx * 8 + 4] = make_float4(acc[i][4], acc[i][5], acc[i][6], acc[i][7]);
        }
    }
}

// ---------------- attention logits ----------------
template <int D>
__global__ __launch_bounds__(256) void k_attn(const float* __restrict__ xw,
                                              const float* __restrict__ as_,
                                              const float* __restrict__ ad_,
                                              float* __restrict__ als,
                                              float* __restrict__ ald) {
    int t = blockIdx.x * 256 + threadIdx.x;
    if (t >= NN * 8) return;
    int n = t >> 3, h = t & 7;
    const float* row = xw + (size_t)n * 8 * D + h * D;
    float s = 0.f, d = 0.f;
#pragma unroll
    for (int i = 0; i < D; i++) {
        float v = __ldg(row + i);
        s += v * __ldg(as_ + h * D + i);
        d += v * __ldg(ad_ + h * D + i);
    }
    als[t] = s;
    ald[t] = d;
}

// ---------------- layer-1 aggregation: warp per dst node ----------------
// lane -> head h = lane>>2, channels c = lane*2, lane*2+1 (64 channels)
// epilogue: h1n = elu(acc/den + b1); optional alpha = ee/den -> alpha_out[eid*8+h]
__global__ __launch_bounds__(256) void k_agg1(const int* __restrict__ off,
                                              const int2* __restrict__ csr,
                                              const float* __restrict__ als,
                                              const float* __restrict__ ald,
                                              const float* __restrict__ xw,
                                              const float* __restrict__ b1,
                                              float* __restrict__ h1n,
                                              float* __restrict__ alpha_out) {
    int node = blockIdx.x * 8 + (threadIdx.x >> 5);
    if (node >= NN) return;
    int lane = threadIdx.x & 31;
    int h = lane >> 2;
    float aldv = __ldg(ald + node * 8 + h);
    int beg = __ldg(off + node), end = __ldg(off + node + 1);
    float acc0 = 0.f, acc1 = 0.f, den = 0.f;
    for (int i = beg; i < end; i++) {
        int2 se = __ldg(csr + i);
        float v = __ldg(als + se.x * 8 + h) + aldv;
        v = v > 0.f ? v : 0.2f * v;            // leaky_relu
        float ee = __expf(v);
        den += ee;
        float2 m = *(const float2*)(xw + (size_t)se.x * 64 + lane * 2);
        acc0 += ee * m.x;
        acc1 += ee * m.y;
    }
    float inv = 1.f / (den + 1e-16f);
    int c = lane * 2;
    float v0 = acc0 * inv + __ldg(b1 + c);
    float v1 = acc1 * inv + __ldg(b1 + c + 1);
    v0 = v0 > 0.f ? v0 : (__expf(v0) - 1.f);   // ELU
    v1 = v1 > 0.f ? v1 : (__expf(v1) - 1.f);
    *(float2*)(h1n + (size_t)node * 64 + c) = make_float2(v0, v1);

    if (alpha_out) {
        // 4 edges per iteration: lane -> edge beg+(lane>>3), head lane&7
        int ha = lane & 7;
        float invh = __shfl_sync(0xffffffffu, inv, ha * 4);  // lane 4h holds den of head h
        float aldva = __ldg(ald + node * 8 + ha);
        for (int i0 = beg; i0 < end; i0 += 4) {
            int i = i0 + (lane >> 3);
            if (i < end) {
                int2 se = __ldg(csr + i);
                float v = __ldg(als + se.x * 8 + ha) + aldva;
                v = v > 0.f ? v : 0.2f * v;
                alpha_out[(size_t)se.y * 8 + ha] = __expf(v) * invh;
            }
        }
    }
}

// ---------------- layer-2 aggregation + bias + log_softmax: warp per dst node ----------------
// lane -> head h = lane>>2, channels c = lane*4..lane*4+3 (128 channels)
__global__ __launch_bounds__(256) void k_agg2(const int* __restrict__ off,
                                              const int2* __restrict__ csr,
                                              const float* __restrict__ als,
                                              const float* __restrict__ ald,
                                              const float* __restrict__ xw,
                                              const float* __restrict__ b2,
                                              float* __restrict__ out) {
    int node = blockIdx.x * 8 + (threadIdx.x >> 5);
    if (node >= NN) return;
    int lane = threadIdx.x & 31;
    int h = lane >> 2;
    float aldv = __ldg(ald + node * 8 + h);
    int beg = __ldg(off + node), end = __ldg(off + node + 1);
    float a0 = 0.f, a1 = 0.f, a2 = 0.f, a3 = 0.f, den = 0.f;
    for (int i = beg; i < end; i++) {
        int2 se = __ldg(csr + i);
        float v = __ldg(als + se.x * 8 + h) + aldv;
        v = v > 0.f ? v : 0.2f * v;
        float ee = __expf(v);
        den += ee;
        float4 m = *(const float4*)(xw + (size_t)se.x * 128 + lane * 4);
        a0 += ee * m.x;
        a1 += ee * m.y;
        a2 += ee * m.z;
        a3 += ee * m.w;
    }
    float inv = 1.f / (den + 1e-16f);
    int c = lane * 4;
    float4 b = *(const float4*)(b2 + c);
    float v0 = a0 * inv + b.x, v1 = a1 * inv + b.y;
    float v2 = a2 * inv + b.z, v3 = a3 * inv + b.w;
    float mx = fmaxf(fmaxf(v0, v1), fmaxf(v2, v3));
#pragma unroll
    for (int o = 16; o > 0; o >>= 1) mx = fmaxf(mx, __shfl_xor_sync(0xffffffffu, mx, o));
    float se_ = __expf(v0 - mx) + __expf(v1 - mx) + __expf(v2 - mx) + __expf(v3 - mx);
#pragma unroll
    for (int o = 16; o > 0; o >>= 1) se_ += __shfl_xor_sync(0xffffffffu, se_, o);
    float ls = mx + __logf(se_);
    *(float4*)(out + (size_t)node * 128 + c) =
        make_float4(v0 - ls, v1 - ls, v2 - ls, v3 - ls);
}

// ---------------- launch ----------------
extern "C" void kernel_launch(void* const* d_in, const int* in_sizes, int n_in,
                              void* d_out, int out_size) {
    const float* x   = (const float*)d_in[0];
    const int*   ei  = (const int*)d_in[1];
    const float* W1  = (const float*)d_in[2];
    const float* a1s = (const float*)d_in[3];
    const float* a1d = (const float*)d_in[4];
    const float* b1  = (const float*)d_in[5];
    const float* W2  = (const float*)d_in[6];
    const float* a2s = (const float*)d_in[7];
    const float* a2d = (const float*)d_in[8];
    const float* b2  = (const float*)d_in[9];

    float* out = (float*)d_out;

    float *xw1, *als1, *ald1, *h1n, *xw2, *als2, *ald2;
    int *cnt, *off, *cur;
    int2 *csr;
    cudaGetSymbolAddress((void**)&xw1,  g_xw1);
    cudaGetSymbolAddress((void**)&als1, g_als1);
    cudaGetSymbolAddress((void**)&ald1, g_ald1);
    cudaGetSymbolAddress((void**)&h1n,  g_h1n);
    cudaGetSymbolAddress((void**)&xw2,  g_xw2);
    cudaGetSymbolAddress((void**)&als2, g_als2);
    cudaGetSymbolAddress((void**)&ald2, g_ald2);
    cudaGetSymbolAddress((void**)&cnt,  g_cnt);
    cudaGetSymbolAddress((void**)&off,  g_off);
    cudaGetSymbolAddress((void**)&cur,  g_cur);
    cudaGetSymbolAddress((void**)&csr,  g_csr);

    cudaMemsetAsync(cnt, 0, (size_t)NN * 4);

    const int gemm_grid = (NN + 127) / 128;
    const int attn_grid = (NN * 8 + 255) / 256;
    const int edge_grid = (ET + 255) / 256;
    const int agg_grid  = (NN + 7) / 8;

    bool want_alpha = (size_t)out_size >= (size_t)NN * 128 + (size_t)ET * 8;
    bool want_logp  = out_size >= NN * 128;

    // CSR build (by destination)
    k_hist<<<edge_grid, 256>>>(ei, cnt);
    k_scan<<<1, 1024>>>(cnt, off, cur);
    k_scatter<<<edge_grid, 256>>>(ei, cur, csr);

    // Layer 1
    k_gemm1<<<gemm_grid, 256>>>(x, W1, xw1);
    k_attn<8><<<attn_grid, 256>>>(xw1, a1s, a1d, als1, ald1);
    k_agg1<<<agg_grid, 256>>>(off, csr, als1, ald1, xw1, b1, h1n,
                              want_alpha ? out + (size_t)NN * 128 : nullptr);

    // Layer 2 (fully fused epilogue: normalize + bias + log_softmax)
    k_gemm2<<<gemm_grid, 256>>>(h1n, W2, xw2);
    k_attn<16><<<attn_grid, 256>>>(xw2, a2s, a2d, als2, ald2);
    if (want_logp) {
        k_agg2<<<agg_grid, 256>>>(off, csr, als2, ald2, xw2, b2, out);
    }
}